// round 3
// baseline (speedup 1.0000x reference)
#include <cuda_runtime.h>
#include <math.h>

#define NG   4
#define NT   4096
#define ND   2048
#define NE   64
#define CAP  128
#define GT   (NG*NT)            // 16384
static const long long GTEC = (long long)GT * NE * CAP;   // 134217728

// ---------------- scratch (device globals; no allocation) ----------------
__device__ float          d_gate1[GT];
__device__ float          d_gate2[GT];
__device__ int            d_e12[GT];       // e1 | (e2<<8)
__device__ unsigned short d_stok[GT];      // sorted token id per rank
__device__ float          d_sumprob[NG*NE];
__device__ float          d_cnt[NG*NE];
__device__ float          d_zsum;

// ---------------- init accumulators ----------------
__global__ void init_accum() {
    int t = threadIdx.x;
    if (t < NG*NE) { d_sumprob[t] = 0.f; d_cnt[t] = 0.f; }
    if (t == 0) d_zsum = 0.f;
}

// ---------------- GEMM + softmax + top-2 + loss partials ----------------
// grid = 256 blocks (64 rows each), 256 threads.
// Accuracy: per-32-chunk fp32 fma accumulation (partial magnitude ~0.1),
// Kahan-compensated fold into the running sum via _rn intrinsics so the
// compensation survives any fast-math compilation. Logit error ~1e-7.
__global__ void __launch_bounds__(256) router_gemm(
    const float* __restrict__ A,   // [GT][ND]
    const float* __restrict__ Wm,  // [ND][NE]
    const float* __restrict__ bias // [NE]
) {
    __shared__ float sA[32][68];   // transposed A chunk [kk][row], padded
    __shared__ float sB[32][64];   // W chunk [kk][e]
    __shared__ float sL[64][65];   // logits tile, then exp() values
    __shared__ float sInv[64];
    __shared__ float sZ[64];
    __shared__ int   sCnt[64];

    const int tid  = threadIdx.x;
    const int row0 = blockIdx.x * 64;
    const int tr   = tid >> 4;     // 0..15, rows 4*tr
    const int tc   = tid & 15;     // 0..15, cols 4*tc

    float sum[4][4], comp[4][4];
#pragma unroll
    for (int i = 0; i < 4; i++)
#pragma unroll
        for (int j = 0; j < 4; j++) { sum[i][j] = 0.f; comp[i][j] = 0.f; }

    for (int d0 = 0; d0 < ND; d0 += 32) {
        // stage A: 64 rows x 32 cols, transposed into sA[kk][row]
#pragma unroll
        for (int it = 0; it < 2; it++) {
            int idx = tid + it * 256;          // 0..511
            int r   = idx >> 3;
            int c4  = (idx & 7) << 2;
            float4 v = *(const float4*)(A + (size_t)(row0 + r) * ND + d0 + c4);
            sA[c4+0][r] = v.x; sA[c4+1][r] = v.y;
            sA[c4+2][r] = v.z; sA[c4+3][r] = v.w;
        }
        // stage B: 32 rows x 64 cols, natural layout
#pragma unroll
        for (int it = 0; it < 2; it++) {
            int idx = tid + it * 256;
            int r   = idx >> 4;
            int c4  = (idx & 15) << 2;
            *(float4*)&sB[r][c4] = *(const float4*)(Wm + (size_t)(d0 + r) * NE + c4);
        }
        __syncthreads();

        float ch[4][4];
#pragma unroll
        for (int i = 0; i < 4; i++)
#pragma unroll
            for (int j = 0; j < 4; j++) ch[i][j] = 0.f;

#pragma unroll
        for (int kk = 0; kk < 32; kk++) {
            float a[4], b[4];
            *(float4*)a = *(const float4*)&sA[kk][tr*4];
            *(float4*)b = *(const float4*)&sB[kk][tc*4];
#pragma unroll
            for (int i = 0; i < 4; i++)
#pragma unroll
                for (int j = 0; j < 4; j++)
                    ch[i][j] = __fmaf_rn(a[i], b[j], ch[i][j]);
        }
        // Kahan fold of the chunk into (sum, comp)
#pragma unroll
        for (int i = 0; i < 4; i++)
#pragma unroll
            for (int j = 0; j < 4; j++) {
                float y = __fsub_rn(ch[i][j], comp[i][j]);
                float t = __fadd_rn(sum[i][j], y);
                comp[i][j] = __fsub_rn(__fsub_rn(t, sum[i][j]), y);
                sum[i][j] = t;
            }
        __syncthreads();
    }

    // write logits (+bias) to shared
#pragma unroll
    for (int i = 0; i < 4; i++)
#pragma unroll
        for (int j = 0; j < 4; j++)
            sL[tr*4 + i][tc*4 + j] = __fadd_rn(sum[i][j], bias[tc*4 + j]);
    if (tid < 64) sCnt[tid] = 0;
    __syncthreads();

    const int g = row0 / NT;

    if (tid < 64) {
        const int r = tid;
        // top-2 by logit (monotone with softmax), ties -> lower index
        float l1 = -INFINITY, l2 = -INFINITY;
        int   e1 = 0, e2 = 0;
        for (int c = 0; c < 64; c++) {
            float l = sL[r][c];
            if (l > l1)      { l2 = l1; e2 = e1; l1 = l; e1 = c; }
            else if (l > l2) { l2 = l;  e2 = c; }
        }
        // softmax stats, sequential order c=0..63 (matches reference math order)
        float s = 0.f, sl = 0.f, sq = 0.f;
        for (int c = 0; c < 64; c++) {
            float l  = sL[r][c];
            float ex = expf(__fsub_rn(l, l1));
            s  = __fadd_rn(s, ex);
            sl += l;
            sq = __fmaf_rn(l, l, sq);
            sL[r][c] = ex;    // keep exp for per-expert prob sums
        }
        const int row = row0 + r;
        float g1 = __fdiv_rn(1.0f, s);                       // exp(0)/s, IEEE div
        float g2 = __fdiv_rn(expf(__fsub_rn(l2, l1)), s);
        d_gate1[row] = g1;
        d_gate2[row] = g2;
        d_e12[row]   = e1 | (e2 << 8);
        sInv[r] = g1;
        atomicAdd(&sCnt[e1], 1);
        atomicAdd(&sCnt[e2], 1);
        float lse = l1 + logf(s);
        sZ[r] = sq - 2.f * lse * sl + 64.f * lse * lse;
    }
    __syncthreads();

    if (tid < 64) {
        const int c = tid;
        float cs = 0.f;
        for (int r = 0; r < 64; r++) cs += sL[r][c] * sInv[r];
        atomicAdd(&d_sumprob[g*64 + c], cs);
        atomicAdd(&d_cnt[g*64 + c], (float)sCnt[c]);
    }
    if (tid == 0) {
        float z = 0.f;
        for (int r = 0; r < 64; r++) z += sZ[r];
        atomicAdd(&d_zsum, z);
    }
}

// ---------------- BPR sort: per-group bitonic, descending by gate1 ----------------
// stable tie-break: smaller token index first -> low word = 0xFFFFFFFF - t
__global__ void __launch_bounds__(1024) bpr_sort() {
    __shared__ unsigned long long sk[NT];   // 32 KB
    const int g   = blockIdx.x;
    const int tid = threadIdx.x;
    for (int r = tid; r < NT; r += 1024) {
        unsigned int gb = __float_as_uint(d_gate1[g*NT + r]);  // positive floats: bits monotone
        sk[r] = ((unsigned long long)gb << 32) | (unsigned int)(0xFFFFFFFFu - (unsigned)r);
    }
    __syncthreads();
    for (int k = 2; k <= NT; k <<= 1) {
        for (int j = k >> 1; j > 0; j >>= 1) {
#pragma unroll 1
            for (int i = tid; i < NT; i += 1024) {
                int ixj = i ^ j;
                if (ixj > i) {
                    unsigned long long a = sk[i], b = sk[ixj];
                    bool desc = ((i & k) == 0);
                    if (desc ? (a < b) : (a > b)) { sk[i] = b; sk[ixj] = a; }
                }
            }
            __syncthreads();
        }
    }
    for (int r = tid; r < NT; r += 1024)
        d_stok[g*NT + r] =
            (unsigned short)(0xFFFFFFFFu - (unsigned int)(sk[r] & 0xFFFFFFFFull));
}

// ---------------- capacity assignment + scatter ----------------
// Per group: warp w owns experts {2w, 2w+1}. Counter runs over the k-major
// concatenation [all top-1 in sorted order, then all top-2] == reference cumsum.
__global__ void __launch_bounds__(1024) assign_scatter(float* __restrict__ out) {
    __shared__ unsigned char  se0[NT];
    __shared__ unsigned char  se1[NT];
    __shared__ unsigned short st[NT];
    const int g   = blockIdx.x;
    const int tid = threadIdx.x;
    for (int r = tid; r < NT; r += 1024) {
        int tok = d_stok[g*NT + r];
        int pk  = d_e12[g*NT + tok];
        se0[r] = (unsigned char)(pk & 0xFF);
        se1[r] = (unsigned char)((pk >> 8) & 0xFF);
        st[r]  = (unsigned short)tok;
    }
    __syncthreads();

    const int w    = tid >> 5;
    const int lane = tid & 31;
    const unsigned lt_mask = (lane == 0) ? 0u : (0xFFFFFFFFu >> (32 - lane));

    for (int half = 0; half < 2; half++) {
        const int e = w * 2 + half;
        int cnt = 0;
        // pass over top-1 choices (sorted order)
        for (int j = 0; j < NT/32; j++) {
            int v = se0[j*32 + lane];
            bool m = (v == e);
            unsigned bal = __ballot_sync(0xFFFFFFFFu, m);
            if (m) {
                int pos = cnt + __popc(bal & lt_mask);
                if (pos < CAP) {
                    int tok = st[j*32 + lane];
                    long long base = ((long long)(g*NT + tok) * NE + e) * CAP + pos;
                    out[base]        = 1.0f;
                    out[GTEC + base] = d_gate1[g*NT + tok];
                }
            }
            cnt += __popc(bal);
        }
        // pass over top-2 choices (counter continues)
        for (int j = 0; j < NT/32; j++) {
            int v = se1[j*32 + lane];
            bool m = (v == e);
            unsigned bal = __ballot_sync(0xFFFFFFFFu, m);
            if (m) {
                int pos = cnt + __popc(bal & lt_mask);
                if (pos < CAP) {
                    int tok = st[j*32 + lane];
                    long long base = ((long long)(g*NT + tok) * NE + e) * CAP + pos;
                    out[base]        = 1.0f;
                    out[GTEC + base] = d_gate2[g*NT + tok];
                }
            }
            cnt += __popc(bal);
        }
    }
}

// ---------------- losses ----------------
__global__ void finalize(float* __restrict__ out) {
    __shared__ float red[256];
    const int t = threadIdx.x;
    red[t] = d_cnt[t] * d_sumprob[t];   // t in [0,256) == NG*NE
    __syncthreads();
    for (int s = 128; s > 0; s >>= 1) {
        if (t < s) red[t] += red[t + s];
        __syncthreads();
    }
    if (t == 0) {
        // aux = E/(G*T^2) * sum_{g,e} cnt*sumprob
        out[2*GTEC]     = red[0] * ((float)NE / ((float)NG * (float)NT * (float)NT));
        out[2*GTEC + 1] = d_zsum / (float)((long long)NG * NT * NE);
    }
}

// ---------------- launch ----------------
extern "C" void kernel_launch(void* const* d_in, const int* in_sizes, int n_in,
                              void* d_out, int out_size) {
    const float* A    = (const float*)d_in[0];   // token_inputs [4,4096,2048]
    const float* Wm   = (const float*)d_in[1];   // W [2048,64]
    const float* bias = (const float*)d_in[2];   // b [64]
    float* out = (float*)d_out;

    // zero the whole (sparse) output: dispatch | combine | aux | z
    cudaMemsetAsync(d_out, 0, (size_t)out_size * sizeof(float), 0);

    init_accum<<<1, 256>>>();
    router_gemm<<<GT/64, 256>>>(A, Wm, bias);
    bpr_sort<<<NG, 1024>>>();
    assign_scatter<<<NG, 1024>>>(out);
    finalize<<<1, 256>>>(out);
}

// round 4
// speedup vs baseline: 1.0092x; 1.0092x over previous
#include <cuda_runtime.h>
#include <math.h>

#define NG   4
#define NT   4096
#define ND   2048
#define NE   64
#define CAP  128
#define GT   (NG*NT)            // 16384
static const long long GTEC = (long long)GT * NE * CAP;   // 134217728

#define GEMM_BLOCKS 256
#define ZERO_BLOCKS 128

// ---------------- scratch (device globals; no allocation) ----------------
__device__ float          d_gate1[GT];
__device__ float          d_gate2[GT];
__device__ int            d_e12[GT];        // e1 | (e2<<8)
__device__ unsigned char  d_se0[GT];        // sorted-order top-1 expert id
__device__ unsigned char  d_se1[GT];        // sorted-order top-2 expert id
__device__ unsigned short d_stok[GT];       // sorted-order token id
__device__ float          d_sumprob[NG*NE];
__device__ float          d_cnt[NG*NE];
__device__ float          d_zsum;

// ---------------- f32x2 packed helpers ----------------
#define FMA_X2(d,a,b,c) asm("fma.rn.f32x2 %0, %1, %2, %3;" : "=l"(d) : "l"(a), "l"(b), "l"(c))
#define ADD_X2(d,a,b)   asm("add.rn.f32x2 %0, %1, %2;"     : "=l"(d) : "l"(a), "l"(b))
#define UNPK_X2(lo,hi,v) asm("mov.b64 {%0,%1}, %2;" : "=r"(lo), "=r"(hi) : "l"(v))

// ---------------- init accumulators ----------------
__global__ void init_accum() {
    int t = threadIdx.x;
    if (t < NG*NE) { d_sumprob[t] = 0.f; d_cnt[t] = 0.f; }
    if (t == 0) d_zsum = 0.f;
}

// ---------------- fused: GEMM(+softmax/top2/losses) blocks + output-zeroing blocks ----------------
// blocks [0,256): 64 logits rows each. blocks [256,384): stream zeros over out.
__global__ void __launch_bounds__(256) fused_gemm_zero(
    const float* __restrict__ A,   // [GT][ND]
    const float* __restrict__ Wm,  // [ND][NE]
    const float* __restrict__ bias,// [NE]
    float* __restrict__ out
) {
    // ---------- zero path ----------
    if (blockIdx.x >= GEMM_BLOCKS) {
        const size_t n4 = (size_t)(2 * GTEC) / 4;            // 67108864 float4s
        const size_t stride = (size_t)ZERO_BLOCKS * 256;
        float4* o4 = (float4*)out;
        const float4 z = make_float4(0.f, 0.f, 0.f, 0.f);
        for (size_t i = (size_t)(blockIdx.x - GEMM_BLOCKS) * 256 + threadIdx.x;
             i < n4; i += stride)
            __stwt(o4 + i, z);
        return;
    }

    // ---------- GEMM path ----------
    __shared__ float sA2[32][132];  // duplicated pairs: [kk][2*row .. 2*row+1] = a
    __shared__ float sB[32][64];    // W chunk [kk][e]
    __shared__ float sL[64][65];    // logits tile, then exp() values
    __shared__ float sInv[64];
    __shared__ float sZ[64];
    __shared__ int   sCnt[64];

    const int tid  = threadIdx.x;
    const int row0 = blockIdx.x * 64;
    const int tr   = tid >> 4;     // 0..15, rows 4*tr
    const int tc   = tid & 15;     // 0..15, cols 4*tc

    unsigned long long m1;         // packed (-1,-1)
    asm("mov.b64 %0, {%1,%2};" : "=l"(m1) : "r"(__float_as_uint(-1.0f)), "r"(__float_as_uint(-1.0f)));

    // packed accumulators: [row i][col pair p] covering cols (4tc+2p, 4tc+2p+1)
    unsigned long long sum[4][2], comp[4][2];
#pragma unroll
    for (int i = 0; i < 4; i++)
#pragma unroll
        for (int p = 0; p < 2; p++) { sum[i][p] = 0ull; comp[i][p] = 0ull; }

    for (int d0 = 0; d0 < ND; d0 += 32) {
        // stage A: 64 rows x 32 cols, transposed + duplicated into sA2[kk][2r]=[2r+1]=a
#pragma unroll
        for (int it = 0; it < 2; it++) {
            int idx = tid + it * 256;          // 0..511
            int r   = idx >> 3;
            int c4  = (idx & 7) << 2;
            float4 v = *(const float4*)(A + (size_t)(row0 + r) * ND + d0 + c4);
            *(float2*)&sA2[c4+0][2*r] = make_float2(v.x, v.x);
            *(float2*)&sA2[c4+1][2*r] = make_float2(v.y, v.y);
            *(float2*)&sA2[c4+2][2*r] = make_float2(v.z, v.z);
            *(float2*)&sA2[c4+3][2*r] = make_float2(v.w, v.w);
        }
        // stage B: 32 rows x 64 cols, natural layout
#pragma unroll
        for (int it = 0; it < 2; it++) {
            int idx = tid + it * 256;
            int r   = idx >> 4;
            int c4  = (idx & 15) << 2;
            *(float4*)&sB[r][c4] = *(const float4*)(Wm + (size_t)(d0 + r) * NE + c4);
        }
        __syncthreads();

        unsigned long long ch[4][2];
#pragma unroll
        for (int i = 0; i < 4; i++)
#pragma unroll
            for (int p = 0; p < 2; p++) ch[i][p] = 0ull;

#pragma unroll
        for (int kk = 0; kk < 32; kk++) {
            const unsigned long long* ap =
                (const unsigned long long*)&sA2[kk][8*tr];   // 4 x (a_i,a_i)
            const unsigned long long* bp =
                (const unsigned long long*)&sB[kk][4*tc];    // (b0,b1),(b2,b3)
            unsigned long long b0 = bp[0], b1 = bp[1];
            unsigned long long a0 = ap[0], a1 = ap[1], a2 = ap[2], a3 = ap[3];
            FMA_X2(ch[0][0], a0, b0, ch[0][0]);
            FMA_X2(ch[0][1], a0, b1, ch[0][1]);
            FMA_X2(ch[1][0], a1, b0, ch[1][0]);
            FMA_X2(ch[1][1], a1, b1, ch[1][1]);
            FMA_X2(ch[2][0], a2, b0, ch[2][0]);
            FMA_X2(ch[2][1], a2, b1, ch[2][1]);
            FMA_X2(ch[3][0], a3, b0, ch[3][0]);
            FMA_X2(ch[3][1], a3, b1, ch[3][1]);
        }
        // Kahan fold of the chunk into (sum, comp), packed.
        // y = ch - comp ; t = sum + y ; comp = (t - sum) - y ; sum = t
        // exact subtractions via fma(x, -1, y).
#pragma unroll
        for (int i = 0; i < 4; i++)
#pragma unroll
            for (int p = 0; p < 2; p++) {
                unsigned long long y, t, tmp;
                FMA_X2(y, comp[i][p], m1, ch[i][p]);
                ADD_X2(t, sum[i][p], y);
                FMA_X2(tmp, sum[i][p], m1, t);
                FMA_X2(comp[i][p], y, m1, tmp);
                sum[i][p] = t;
            }
        __syncthreads();
    }

    // write logits (+bias) to shared
#pragma unroll
    for (int i = 0; i < 4; i++)
#pragma unroll
        for (int p = 0; p < 2; p++) {
            unsigned int ulo, uhi;
            UNPK_X2(ulo, uhi, sum[i][p]);
            sL[tr*4 + i][tc*4 + 2*p + 0] = __fadd_rn(__uint_as_float(ulo), bias[tc*4 + 2*p + 0]);
            sL[tr*4 + i][tc*4 + 2*p + 1] = __fadd_rn(__uint_as_float(uhi), bias[tc*4 + 2*p + 1]);
        }
    if (tid < 64) sCnt[tid] = 0;
    __syncthreads();

    const int g = row0 / NT;

    if (tid < 64) {
        const int r = tid;
        // top-2 by logit (monotone with softmax), ties -> lower index
        float l1 = -INFINITY, l2 = -INFINITY;
        int   e1 = 0, e2 = 0;
        for (int c = 0; c < 64; c++) {
            float l = sL[r][c];
            if (l > l1)      { l2 = l1; e2 = e1; l1 = l; e1 = c; }
            else if (l > l2) { l2 = l;  e2 = c; }
        }
        // softmax stats, sequential order c=0..63
        float s = 0.f, sl = 0.f, sq = 0.f;
        for (int c = 0; c < 64; c++) {
            float l  = sL[r][c];
            float ex = expf(__fsub_rn(l, l1));
            s  = __fadd_rn(s, ex);
            sl += l;
            sq = __fmaf_rn(l, l, sq);
            sL[r][c] = ex;    // keep exp for per-expert prob sums
        }
        const int row = row0 + r;
        float g1 = __fdiv_rn(1.0f, s);                       // exp(0)/s, IEEE div
        float g2 = __fdiv_rn(expf(__fsub_rn(l2, l1)), s);
        d_gate1[row] = g1;
        d_gate2[row] = g2;
        d_e12[row]   = e1 | (e2 << 8);
        sInv[r] = g1;
        atomicAdd(&sCnt[e1], 1);
        atomicAdd(&sCnt[e2], 1);
        float lse = l1 + logf(s);
        sZ[r] = sq - 2.f * lse * sl + 64.f * lse * lse;
    }
    __syncthreads();

    if (tid < 64) {
        const int c = tid;
        float cs = 0.f;
        for (int r = 0; r < 64; r++) cs += sL[r][c] * sInv[r];
        atomicAdd(&d_sumprob[g*64 + c], cs);
        atomicAdd(&d_cnt[g*64 + c], (float)sCnt[c]);
    }
    if (tid == 0) {
        float z = 0.f;
        for (int r = 0; r < 64; r++) z += sZ[r];
        atomicAdd(&d_zsum, z);
    }
}

// ---------------- BPR sort: per-group bitonic, descending by gate1 ----------------
// stable tie-break: smaller token index first -> low word = 0xFFFFFFFF - t
// Epilogue writes sorted-order expert streams for the assign kernel.
__global__ void __launch_bounds__(1024) bpr_sort() {
    __shared__ unsigned long long sk[NT];   // 32 KB
    const int g   = blockIdx.x;
    const int tid = threadIdx.x;
    for (int r = tid; r < NT; r += 1024) {
        unsigned int gb = __float_as_uint(d_gate1[g*NT + r]);  // positive floats: bits monotone
        sk[r] = ((unsigned long long)gb << 32) | (unsigned int)(0xFFFFFFFFu - (unsigned)r);
    }
    __syncthreads();
    for (int k = 2; k <= NT; k <<= 1) {
        for (int j = k >> 1; j > 0; j >>= 1) {
#pragma unroll 1
            for (int i = tid; i < NT; i += 1024) {
                int ixj = i ^ j;
                if (ixj > i) {
                    unsigned long long a = sk[i], b = sk[ixj];
                    bool desc = ((i & k) == 0);
                    if (desc ? (a < b) : (a > b)) { sk[i] = b; sk[ixj] = a; }
                }
            }
            __syncthreads();
        }
    }
    for (int r = tid; r < NT; r += 1024) {
        int tok = (int)(0xFFFFFFFFu - (unsigned int)(sk[r] & 0xFFFFFFFFull));
        int pk  = d_e12[g*NT + tok];
        d_stok[g*NT + r] = (unsigned short)tok;
        d_se0[g*NT + r]  = (unsigned char)(pk & 0xFF);
        d_se1[g*NT + r]  = (unsigned char)((pk >> 8) & 0xFF);
    }
}

// ---------------- capacity assignment + sparse scatter ----------------
// grid (NG, 2) x 1024 threads: warp w of block (g,h) owns expert h*32+w.
// Counter runs over the k-major concatenation [all top-1 sorted, then all top-2]
// == reference cumsum semantics.
__global__ void __launch_bounds__(1024) assign_scatter(float* __restrict__ out) {
    const int g    = blockIdx.x;
    const int e    = blockIdx.y * 32 + (threadIdx.x >> 5);
    const int lane = threadIdx.x & 31;
    const unsigned lt_mask = (lane == 0) ? 0u : (0xFFFFFFFFu >> (32 - lane));

    const unsigned char* streams[2] = { d_se0 + g*NT, d_se1 + g*NT };
    int cnt = 0;
    for (int pass = 0; pass < 2; pass++) {
        const unsigned char* se = streams[pass];
        const float* gate = pass ? d_gate2 : d_gate1;
        for (int j = 0; j < NT/32; j++) {
            int v = se[j*32 + lane];
            bool m = (v == e);
            unsigned bal = __ballot_sync(0xFFFFFFFFu, m);
            if (m) {
                int pos = cnt + __popc(bal & lt_mask);
                if (pos < CAP) {
                    int tok = d_stok[g*NT + j*32 + lane];
                    long long base = ((long long)(g*NT + tok) * NE + e) * CAP + pos;
                    out[base]        = 1.0f;
                    out[GTEC + base] = gate[g*NT + tok];
                }
            }
            cnt += __popc(bal);
        }
    }
}

// ---------------- losses ----------------
__global__ void finalize(float* __restrict__ out) {
    __shared__ float red[256];
    const int t = threadIdx.x;
    red[t] = d_cnt[t] * d_sumprob[t];   // t in [0,256) == NG*NE
    __syncthreads();
    for (int s = 128; s > 0; s >>= 1) {
        if (t < s) red[t] += red[t + s];
        __syncthreads();
    }
    if (t == 0) {
        // aux = E/(G*T^2) * sum_{g,e} cnt*sumprob
        out[2*GTEC]     = red[0] * ((float)NE / ((float)NG * (float)NT * (float)NT));
        out[2*GTEC + 1] = d_zsum / (float)((long long)NG * NT * NE);
    }
}

// ---------------- launch ----------------
extern "C" void kernel_launch(void* const* d_in, const int* in_sizes, int n_in,
                              void* d_out, int out_size) {
    const float* A    = (const float*)d_in[0];   // token_inputs [4,4096,2048]
    const float* Wm   = (const float*)d_in[1];   // W [2048,64]
    const float* bias = (const float*)d_in[2];   // b [64]
    float* out = (float*)d_out;

    init_accum<<<1, 256>>>();
    fused_gemm_zero<<<GEMM_BLOCKS + ZERO_BLOCKS, 256>>>(A, Wm, bias, out);
    bpr_sort<<<NG, 1024>>>();
    assign_scatter<<<dim3(NG, 2), 1024>>>(out);
    finalize<<<1, 256>>>(out);
}